// round 7
// baseline (speedup 1.0000x reference)
#include <cuda_runtime.h>

// UndistortLayer: B=16, C=3, H=W=512, fp32.
// 1 thread = 2 vertically adjacent pixels (same x). Lanes consecutive in x
// (warp x-span 32 -> ~2 L1 wavefronts per gather LDG, measured optimal).
// Map: px=x-dx-256, d=1-(k/512^2)(px^2+py^2), xd=px/d+cx, yd=py/d+cy.
// xd,yd provably in [0,511] (k<0 contraction) -> one-sided clamps only.
// Corner pointers derived from p00 by small adds; channel planes fold into
// LDG immediate offsets.

#define UD_W 512
#define UD_HW (512 * 512)            // 2^18
#define UD_CHW (3 * UD_HW)

__global__ __launch_bounds__(256) void undistort_kernel(
    const float* __restrict__ im,   // [B, 3, H, W]
    const float* __restrict__ kArr, // [B]
    const float* __restrict__ dxArr,// [B]
    const float* __restrict__ dyArr,// [B]
    float* __restrict__ out)        // [B, 3, H, W]
{
    const int t  = blockIdx.x * 256 + threadIdx.x;
    const int x  = t & 511;               // lane-consecutive x
    const int yp = (t >> 9) & 255;        // y-pair index
    const int b  = t >> 17;
    const int y0 = yp << 1;

    const float k  = __ldg(&kArr[b]);
    const float dx = __ldg(&dxArr[b]);
    const float dy = __ldg(&dyArr[b]);

    const float kw = k * (1.0f / (512.0f * 512.0f));
    const float cx = 256.0f + dx;
    const float cy = 256.0f + dy;
    const float px = (float)x - cx;
    const float px2 = px * px;

    const float* imb = im + (size_t)b * UD_CHW;
    float* outb = out + (size_t)b * UD_CHW + (size_t)y0 * UD_W + x;

    #pragma unroll
    for (int iy = 0; iy < 2; ++iy) {
        const float py = (float)(y0 + iy) - cy;
        const float d  = fmaf(-kw, fmaf(py, py, px2), 1.0f);
        const float inv = __fdividef(1.0f, d);
        const float xd = fmaf(px, inv, cx);
        const float yd = fmaf(py, inv, cy);

        const int xfu = __float2int_rd(xd);
        const int yfu = __float2int_rd(yd);
        const float ox = xd - (float)xfu;
        const float oy = yd - (float)yfu;

        // xd,yd in [0,511] up to 1-ulp rounding -> one-sided clamps.
        const int xfi = max(xfu, 0);
        const int xci = min(xfu + 1, 511);
        const int yfi = max(yfu, 0);
        const int yci = min(yfu + 1, 511);

        const int xs = xci - xfi;          // 0 or 1
        const int ys = (yci - yfi) << 9;   // 0 or 512

        const float* p00 = imb + (yfi << 9) + xfi;
        const float* p01 = p00 + xs;
        const float* p10 = p00 + ys;
        const float* p11 = p10 + xs;

        const float w00 = (1.0f - ox) * (1.0f - oy);
        const float w01 = ox * (1.0f - oy);
        const float w10 = (1.0f - ox) * oy;
        const float w11 = ox * oy;

        float* orow = outb + iy * UD_W;
        #pragma unroll
        for (int c = 0; c < 3; ++c) {
            const float v00 = __ldg(p00 + c * UD_HW);
            const float v01 = __ldg(p01 + c * UD_HW);
            const float v10 = __ldg(p10 + c * UD_HW);
            const float v11 = __ldg(p11 + c * UD_HW);
            orow[c * UD_HW] = fmaf(w00, v00, fmaf(w01, v01, fmaf(w10, v10, w11 * v11)));
        }
    }
}

extern "C" void kernel_launch(void* const* d_in, const int* in_sizes, int n_in,
                              void* d_out, int out_size) {
    const float* im = (const float*)d_in[0];
    const float* k  = (const float*)d_in[1];
    const float* dx = (const float*)d_in[2];
    const float* dy = (const float*)d_in[3];
    float* out = (float*)d_out;

    const int total_threads = 16 * UD_HW / 2;   // 2,097,152
    const int block = 256;
    const int grid = total_threads / block;     // 8192
    undistort_kernel<<<grid, block>>>(im, k, dx, dy, out);
}

// round 8
// speedup vs baseline: 1.0573x; 1.0573x over previous
#include <cuda_runtime.h>

// UndistortLayer: B=16, C=3, H=W=512, fp32.
// 1 thread = 2 vertically adjacent pixels (same x). Lanes consecutive in x.
// Map: px=x-dx-256, d=1-(k/512^2)(px^2+py^2), xd=px/d+cx, yd=py/d+cy.
// One-sided clamps (k<0 contraction keeps xd,yd in [0,511]).
// All index math 32-bit; both pixels' addresses computed BEFORE any gather
// so 24 loads are in flight together (latency hiding).

#define UD_W 512
#define UD_HW (512 * 512)            // 2^18
#define UD_CHW (3 * UD_HW)

__global__ __launch_bounds__(256) void undistort_kernel(
    const float* __restrict__ im,   // [B, 3, H, W]
    const float* __restrict__ kArr, // [B]
    const float* __restrict__ dxArr,// [B]
    const float* __restrict__ dyArr,// [B]
    float* __restrict__ out)        // [B, 3, H, W]
{
    const int t  = blockIdx.x * 256 + threadIdx.x;
    const int x  = t & 511;               // lane-consecutive x
    const int yp = (t >> 9) & 255;        // y-pair index
    const int b  = t >> 17;
    const int y0 = yp << 1;

    const float k  = __ldg(&kArr[b]);
    const float dx = __ldg(&dxArr[b]);
    const float dy = __ldg(&dyArr[b]);

    const float kw = k * (1.0f / (512.0f * 512.0f));
    const float cx = 256.0f + dx;
    const float cy = 256.0f + dy;
    const float px = (float)x - cx;
    const float px2 = px * px;

    const float* imb = im + (size_t)b * UD_CHW;
    float* outb = out + (size_t)b * UD_CHW + (size_t)y0 * UD_W + x;

    // ---- Phase 1: indices + weights for both pixels (no loads yet) ----
    int idx[2][4];
    float wgt[2][4];

    #pragma unroll
    for (int iy = 0; iy < 2; ++iy) {
        const float py = (float)(y0 + iy) - cy;
        const float d  = fmaf(-kw, fmaf(py, py, px2), 1.0f);
        const float inv = __fdividef(1.0f, d);
        const float xd = fmaf(px, inv, cx);
        const float yd = fmaf(py, inv, cy);

        const int xfu = __float2int_rd(xd);
        const int yfu = __float2int_rd(yd);
        const float ox = xd - (float)xfu;
        const float oy = yd - (float)yfu;

        const int xfi = max(xfu, 0);
        const int yfi = max(yfu, 0);
        const int xs  = min(xfu + 1, 511) - xfi;        // 0 or 1
        const int ys  = (min(yfu + 1, 511) - yfi) << 9; // 0 or 512

        const int i00 = (yfi << 9) + xfi;
        idx[iy][0] = i00;
        idx[iy][1] = i00 + xs;
        idx[iy][2] = i00 + ys;
        idx[iy][3] = i00 + ys + xs;

        wgt[iy][0] = (1.0f - ox) * (1.0f - oy);
        wgt[iy][1] = ox * (1.0f - oy);
        wgt[iy][2] = (1.0f - ox) * oy;
        wgt[iy][3] = ox * oy;
    }

    // ---- Phase 2: issue all 24 gathers, then reduce ----
    float v[2][3][4];
    #pragma unroll
    for (int iy = 0; iy < 2; ++iy)
        #pragma unroll
        for (int c = 0; c < 3; ++c) {
            const float* pl = imb + c * UD_HW;
            #pragma unroll
            for (int q = 0; q < 4; ++q)
                v[iy][c][q] = __ldg(pl + idx[iy][q]);
        }

    #pragma unroll
    for (int iy = 0; iy < 2; ++iy) {
        float* orow = outb + iy * UD_W;
        #pragma unroll
        for (int c = 0; c < 3; ++c) {
            orow[c * UD_HW] =
                fmaf(wgt[iy][0], v[iy][c][0],
                fmaf(wgt[iy][1], v[iy][c][1],
                fmaf(wgt[iy][2], v[iy][c][2],
                     wgt[iy][3] * v[iy][c][3])));
        }
    }
}

extern "C" void kernel_launch(void* const* d_in, const int* in_sizes, int n_in,
                              void* d_out, int out_size) {
    const float* im = (const float*)d_in[0];
    const float* k  = (const float*)d_in[1];
    const float* dx = (const float*)d_in[2];
    const float* dy = (const float*)d_in[3];
    float* out = (float*)d_out;

    const int total_threads = 16 * UD_HW / 2;   // 2,097,152
    const int block = 256;
    const int grid = total_threads / block;     // 8192
    undistort_kernel<<<grid, block>>>(im, k, dx, dy, out);
}

// round 9
// speedup vs baseline: 1.1512x; 1.0888x over previous
#include <cuda_runtime.h>

// UndistortLayer: B=16, C=3, H=W=512, fp32.
// 1 thread = 4 vertically adjacent pixels (same x). Lanes consecutive in x
// (warp x-span 32 -> minimal ~2 L1 wavefronts per gather LDG).
// Map: px=x-dx-256, d=1-(k/512^2)(px^2+py^2), xd=px/d+cx, yd=py/d+cy.
// One-sided clamps (k<0 contraction keeps xd,yd within [0,511]).
// Phase 1 computes all 4 rows' indices+weights (ALU burst), phase 2 does
// per-row 12-gather + reduce + 3 stores; scoreboard overlaps rows.

#define UD_W 512
#define UD_HW (512 * 512)            // 2^18
#define UD_CHW (3 * UD_HW)
#define ROWS 4

__global__ __launch_bounds__(256) void undistort_kernel(
    const float* __restrict__ im,   // [B, 3, H, W]
    const float* __restrict__ kArr, // [B]
    const float* __restrict__ dxArr,// [B]
    const float* __restrict__ dyArr,// [B]
    float* __restrict__ out)        // [B, 3, H, W]
{
    const int t  = blockIdx.x * 256 + threadIdx.x;
    const int x  = t & 511;               // lane-consecutive x
    const int yq = (t >> 9) & 127;        // y-quad index
    const int b  = t >> 16;
    const int y0 = yq << 2;

    const float k  = __ldg(&kArr[b]);
    const float dx = __ldg(&dxArr[b]);
    const float dy = __ldg(&dyArr[b]);

    const float kw = k * (1.0f / (512.0f * 512.0f));
    const float cx = 256.0f + dx;
    const float cy = 256.0f + dy;
    const float px = (float)x - cx;
    const float px2 = px * px;

    const float* imb = im + (size_t)b * UD_CHW;
    float* outb = out + (size_t)b * UD_CHW + (size_t)y0 * UD_W + x;

    // ---- Phase 1: indices + weights for all 4 rows ----
    int i00a[ROWS], xsa[ROWS], ysa[ROWS];
    float w00a[ROWS], w01a[ROWS], w10a[ROWS], w11a[ROWS];

    #pragma unroll
    for (int iy = 0; iy < ROWS; ++iy) {
        const float py = (float)(y0 + iy) - cy;
        const float d  = fmaf(-kw, fmaf(py, py, px2), 1.0f);
        const float inv = __fdividef(1.0f, d);
        const float xd = fmaf(px, inv, cx);
        const float yd = fmaf(py, inv, cy);

        const int xfu = __float2int_rd(xd);
        const int yfu = __float2int_rd(yd);
        const float ox = xd - (float)xfu;
        const float oy = yd - (float)yfu;

        const int xfi = max(xfu, 0);
        const int yfi = max(yfu, 0);
        xsa[iy] = min(xfu + 1, 511) - xfi;               // 0 or 1
        ysa[iy] = (min(yfu + 1, 511) - yfi) << 9;        // 0 or 512
        i00a[iy] = (yfi << 9) + xfi;

        w00a[iy] = (1.0f - ox) * (1.0f - oy);
        w01a[iy] = ox * (1.0f - oy);
        w10a[iy] = (1.0f - ox) * oy;
        w11a[iy] = ox * oy;
    }

    // ---- Phase 2: per-row gather + reduce + store ----
    #pragma unroll
    for (int iy = 0; iy < ROWS; ++iy) {
        const int i00 = i00a[iy];
        const int i01 = i00 + xsa[iy];
        const int i10 = i00 + ysa[iy];
        const int i11 = i10 + xsa[iy];

        float v[3][4];
        #pragma unroll
        for (int c = 0; c < 3; ++c) {
            const float* pl = imb + c * UD_HW;
            v[c][0] = __ldg(pl + i00);
            v[c][1] = __ldg(pl + i01);
            v[c][2] = __ldg(pl + i10);
            v[c][3] = __ldg(pl + i11);
        }

        float* orow = outb + iy * UD_W;
        #pragma unroll
        for (int c = 0; c < 3; ++c) {
            orow[c * UD_HW] =
                fmaf(w00a[iy], v[c][0],
                fmaf(w01a[iy], v[c][1],
                fmaf(w10a[iy], v[c][2],
                     w11a[iy] * v[c][3])));
        }
    }
}

extern "C" void kernel_launch(void* const* d_in, const int* in_sizes, int n_in,
                              void* d_out, int out_size) {
    const float* im = (const float*)d_in[0];
    const float* k  = (const float*)d_in[1];
    const float* dx = (const float*)d_in[2];
    const float* dy = (const float*)d_in[3];
    float* out = (float*)d_out;

    const int total_threads = 16 * UD_HW / ROWS;   // 1,048,576
    const int block = 256;
    const int grid = total_threads / block;        // 4096
    undistort_kernel<<<grid, block>>>(im, k, dx, dy, out);
}

// round 10
// speedup vs baseline: 1.2969x; 1.1266x over previous
#include <cuda_runtime.h>

// UndistortLayer: B=16, C=3, H=W=512, fp32.
// 1 thread = 8 vertically adjacent pixels (same x). Lanes consecutive in x
// (warp x-span 32 -> ~2 L1 wavefronts per gather LDG, measured optimal).
// Map: px=x-dx-256, d=1-(k/512^2)(px^2+py^2), xd=px/d+cx, yd=py/d+cy.
// One-sided clamps (k<0 contraction keeps xd,yd in [0,511]).
// Gathers use L1::evict_last (source lines are shared across warps);
// stores use .cs streaming (output never re-read -> don't pollute L1).

#define UD_W 512
#define UD_HW (512 * 512)            // 2^18
#define UD_CHW (3 * UD_HW)
#define ROWS 8

__device__ __forceinline__ float ldg_el(const float* p) {
    float v;
    asm("ld.global.nc.L1::evict_last.f32 %0, [%1];" : "=f"(v) : "l"(p));
    return v;
}
__device__ __forceinline__ void stg_cs(float* p, float v) {
    asm volatile("st.global.cs.f32 [%0], %1;" :: "l"(p), "f"(v));
}

__global__ __launch_bounds__(256) void undistort_kernel(
    const float* __restrict__ im,   // [B, 3, H, W]
    const float* __restrict__ kArr, // [B]
    const float* __restrict__ dxArr,// [B]
    const float* __restrict__ dyArr,// [B]
    float* __restrict__ out)        // [B, 3, H, W]
{
    const int t  = blockIdx.x * 256 + threadIdx.x;
    const int x  = t & 511;               // lane-consecutive x
    const int yo = (t >> 9) & 63;         // y-octet index
    const int b  = t >> 15;
    const int y0 = yo << 3;

    const float k  = __ldg(&kArr[b]);
    const float dx = __ldg(&dxArr[b]);
    const float dy = __ldg(&dyArr[b]);

    const float kw = k * (1.0f / (512.0f * 512.0f));
    const float cx = 256.0f + dx;
    const float cy = 256.0f + dy;
    const float px = (float)x - cx;
    const float px2 = px * px;

    const float* imb = im + (size_t)b * UD_CHW;
    float* outb = out + (size_t)b * UD_CHW + (size_t)y0 * UD_W + x;

    #pragma unroll
    for (int iy = 0; iy < ROWS; ++iy) {
        const float py = (float)(y0 + iy) - cy;
        const float d  = fmaf(-kw, fmaf(py, py, px2), 1.0f);
        const float inv = __fdividef(1.0f, d);
        const float xd = fmaf(px, inv, cx);
        const float yd = fmaf(py, inv, cy);

        const int xfu = __float2int_rd(xd);
        const int yfu = __float2int_rd(yd);
        const float ox = xd - (float)xfu;
        const float oy = yd - (float)yfu;

        const int xfi = max(xfu, 0);
        const int yfi = max(yfu, 0);
        const int xs  = min(xfu + 1, 511) - xfi;        // 0 or 1
        const int ys  = (min(yfu + 1, 511) - yfi) << 9; // 0 or 512

        const int i00 = (yfi << 9) + xfi;
        const int i01 = i00 + xs;
        const int i10 = i00 + ys;
        const int i11 = i10 + xs;

        const float w00 = (1.0f - ox) * (1.0f - oy);
        const float w01 = ox * (1.0f - oy);
        const float w10 = (1.0f - ox) * oy;
        const float w11 = ox * oy;

        float v[3][4];
        #pragma unroll
        for (int c = 0; c < 3; ++c) {
            const float* pl = imb + c * UD_HW;
            v[c][0] = ldg_el(pl + i00);
            v[c][1] = ldg_el(pl + i01);
            v[c][2] = ldg_el(pl + i10);
            v[c][3] = ldg_el(pl + i11);
        }

        float* orow = outb + iy * UD_W;
        #pragma unroll
        for (int c = 0; c < 3; ++c) {
            stg_cs(orow + c * UD_HW,
                   fmaf(w00, v[c][0],
                   fmaf(w01, v[c][1],
                   fmaf(w10, v[c][2],
                        w11 * v[c][3]))));
        }
    }
}

extern "C" void kernel_launch(void* const* d_in, const int* in_sizes, int n_in,
                              void* d_out, int out_size) {
    const float* im = (const float*)d_in[0];
    const float* k  = (const float*)d_in[1];
    const float* dx = (const float*)d_in[2];
    const float* dy = (const float*)d_in[3];
    float* out = (float*)d_out;

    const int total_threads = 16 * UD_HW / ROWS;   // 524,288
    const int block = 256;
    const int grid = total_threads / block;        // 2048
    undistort_kernel<<<grid, block>>>(im, k, dx, dy, out);
}

// round 11
// speedup vs baseline: 1.3696x; 1.0561x over previous
#include <cuda_runtime.h>

// UndistortLayer: B=16, C=3, H=W=512, fp32.
// 1 thread = 8 vertically adjacent pixels (same x), processed in 4 row-PAIRS:
// both rows' indices+weights computed, all 24 gathers issued together (2x MLP),
// then both rows reduced. Lanes consecutive in x (warp x-span 32).
// Map: px=x-dx-256, d=1-(k/512^2)(px^2+py^2), xd=px/d+cx, yd=py/d+cy.
// One-sided clamps (k<0 contraction keeps xd,yd in [0,511]).
// Gathers: L1::evict_last (lines shared across warps). Stores: .cs streaming.

#define UD_W 512
#define UD_HW (512 * 512)            // 2^18
#define UD_CHW (3 * UD_HW)
#define ROWS 8

__device__ __forceinline__ float ldg_el(const float* p) {
    float v;
    asm("ld.global.nc.L1::evict_last.f32 %0, [%1];" : "=f"(v) : "l"(p));
    return v;
}
__device__ __forceinline__ void stg_cs(float* p, float v) {
    asm volatile("st.global.cs.f32 [%0], %1;" :: "l"(p), "f"(v));
}

__global__ __launch_bounds__(256) void undistort_kernel(
    const float* __restrict__ im,   // [B, 3, H, W]
    const float* __restrict__ kArr, // [B]
    const float* __restrict__ dxArr,// [B]
    const float* __restrict__ dyArr,// [B]
    float* __restrict__ out)        // [B, 3, H, W]
{
    const int t  = blockIdx.x * 256 + threadIdx.x;
    const int x  = t & 511;               // lane-consecutive x
    const int yo = (t >> 9) & 63;         // y-octet index
    const int b  = t >> 15;
    const int y0 = yo << 3;

    const float k  = __ldg(&kArr[b]);
    const float dx = __ldg(&dxArr[b]);
    const float dy = __ldg(&dyArr[b]);

    const float kw = k * (1.0f / (512.0f * 512.0f));
    const float cx = 256.0f + dx;
    const float cy = 256.0f + dy;
    const float px = (float)x - cx;
    const float px2 = px * px;

    const float* imb = im + (size_t)b * UD_CHW;
    float* outb = out + (size_t)b * UD_CHW + (size_t)y0 * UD_W + x;

    float py = (float)y0 - cy;

    #pragma unroll
    for (int ip = 0; ip < ROWS / 2; ++ip) {
        // ---- indices + weights for the row pair ----
        int i00p[2], xsp[2], ysp[2];
        float w00p[2], w01p[2], w10p[2], w11p[2];

        #pragma unroll
        for (int r = 0; r < 2; ++r) {
            const float d  = fmaf(-kw, fmaf(py, py, px2), 1.0f);
            const float inv = __fdividef(1.0f, d);
            const float xd = fmaf(px, inv, cx);
            const float yd = fmaf(py, inv, cy);
            py += 1.0f;

            const int xfu = __float2int_rd(xd);
            const int yfu = __float2int_rd(yd);
            const float ox = xd - (float)xfu;
            const float oy = yd - (float)yfu;

            const int xfi = max(xfu, 0);
            const int yfi = max(yfu, 0);
            xsp[r] = min(xfu + 1, 511) - xfi;               // 0 or 1
            ysp[r] = (min(yfu + 1, 511) - yfi) << 9;        // 0 or 512
            i00p[r] = (yfi << 9) + xfi;

            w00p[r] = (1.0f - ox) * (1.0f - oy);
            w01p[r] = ox * (1.0f - oy);
            w10p[r] = (1.0f - ox) * oy;
            w11p[r] = ox * oy;
        }

        // ---- issue all 24 gathers for both rows ----
        float v[2][3][4];
        #pragma unroll
        for (int r = 0; r < 2; ++r) {
            const int i00 = i00p[r];
            const int i01 = i00 + xsp[r];
            const int i10 = i00 + ysp[r];
            const int i11 = i10 + xsp[r];
            #pragma unroll
            for (int c = 0; c < 3; ++c) {
                const float* pl = imb + c * UD_HW;
                v[r][c][0] = ldg_el(pl + i00);
                v[r][c][1] = ldg_el(pl + i01);
                v[r][c][2] = ldg_el(pl + i10);
                v[r][c][3] = ldg_el(pl + i11);
            }
        }

        // ---- reduce + store both rows ----
        #pragma unroll
        for (int r = 0; r < 2; ++r) {
            float* orow = outb + (2 * ip + r) * UD_W;
            #pragma unroll
            for (int c = 0; c < 3; ++c) {
                stg_cs(orow + c * UD_HW,
                       fmaf(w00p[r], v[r][c][0],
                       fmaf(w01p[r], v[r][c][1],
                       fmaf(w10p[r], v[r][c][2],
                            w11p[r] * v[r][c][3]))));
            }
        }
    }
}

extern "C" void kernel_launch(void* const* d_in, const int* in_sizes, int n_in,
                              void* d_out, int out_size) {
    const float* im = (const float*)d_in[0];
    const float* k  = (const float*)d_in[1];
    const float* dx = (const float*)d_in[2];
    const float* dy = (const float*)d_in[3];
    float* out = (float*)d_out;

    const int total_threads = 16 * UD_HW / ROWS;   // 524,288
    const int block = 256;
    const int grid = total_threads / block;        // 2048
    undistort_kernel<<<grid, block>>>(im, k, dx, dy, out);
}